// round 13
// baseline (speedup 1.0000x reference)
#include <cuda_runtime.h>
#include <cuda_fp16.h>
#include <cstdint>
#include <math.h>

#define BATCH 8192
#define SDIM  268
#define HDIM  1024
#define RB    8
#define ADIM  256
#define ZDIM  8
#define EDIM  4
#define KX    288   /* 270 padded to multiple of 32 */

#define CDIV(a,b) (((a)+(b)-1)/(b))
#define EPI_NONE 0
#define EPI_RELU 1
#define EPI_TANH 2

// ---- standalone GEMM (R9 config): CTA 128x128, 8 warps 64x32, KC 32 ----
#define G_KC     32
#define G_RSTR   80
#define G_OFFB   10240
#define G_STG    20480
#define G_NST    4
#define G_SMEM   (G_NST*G_STG)      /* 81920 */

// ---- fused residual block kernel ----
#define R_STG    25600              /* A 64*80 + B 256*80 */
#define R_PHB    5120               /* B offset inside stage */
#define R_NST    3
#define R_USTR   2064               /* u row stride: 2048 + 16 pad */
#define R_UOFF   (R_NST*R_STG)      /* 76800 */
#define R_SMEM   (R_UOFF + 64*R_USTR)  /* 208896 */

// ---------------------------------------------------------------------------
// Scratch (static __device__ arrays; no allocation anywhere)
// ---------------------------------------------------------------------------
__device__ __align__(16) __half g_x [BATCH*KX];
__device__ __align__(16) __half g_hA[BATCH*HDIM];
__device__ __align__(16) __half g_hB[BATCH*HDIM];
__device__ __align__(16) __half g_v [BATCH*ADIM];
__device__ __align__(16) float  g_dh[BATCH*ADIM];
__device__ __align__(16) float  g_dloc[BATCH*ZDIM];

__device__ __align__(16) __half g_W0[HDIM*KX];
__device__ __align__(16) __half g_W1[RB*HDIM*HDIM];
__device__ __align__(16) __half g_W2[RB*HDIM*HDIM];
__device__ __align__(16) __half g_Wf[SDIM*HDIM];
__device__ __align__(16) __half g_TI[ADIM*ADIM];
__device__ __align__(16) __half g_TO[ADIM*ADIM];

// ---------------------------------------------------------------------------
// Helpers
// ---------------------------------------------------------------------------
__device__ __forceinline__ float tanh_fast(float x) {
    float e = __expf(2.0f * x);
    return 1.0f - __fdividef(2.0f, e + 1.0f);   // NaN-safe
}
__device__ __forceinline__ uint32_t smem_u32(const void* p) {
    uint32_t a;
    asm("{ .reg .u64 t; cvta.to.shared.u64 t, %1; cvt.u32.u64 %0, t; }" : "=r"(a) : "l"(p));
    return a;
}
__device__ __forceinline__ void ldm4(unsigned r[4], uint32_t addr) {
    asm volatile("ldmatrix.sync.aligned.m8n8.x4.shared.b16 {%0,%1,%2,%3}, [%4];"
                 : "=r"(r[0]), "=r"(r[1]), "=r"(r[2]), "=r"(r[3]) : "r"(addr));
}
__device__ __forceinline__ void ldm2(unsigned r[2], uint32_t addr) {
    asm volatile("ldmatrix.sync.aligned.m8n8.x2.shared.b16 {%0,%1}, [%2];"
                 : "=r"(r[0]), "=r"(r[1]) : "r"(addr));
}
__device__ __forceinline__ void mma_f16(float c[4], const unsigned a[4], const unsigned b[2]) {
    asm volatile(
        "mma.sync.aligned.m16n8k16.row.col.f32.f16.f16.f32 "
        "{%0,%1,%2,%3}, {%4,%5,%6,%7}, {%8,%9}, {%0,%1,%2,%3};"
        : "+f"(c[0]), "+f"(c[1]), "+f"(c[2]), "+f"(c[3])
        : "r"(a[0]), "r"(a[1]), "r"(a[2]), "r"(a[3]), "r"(b[0]), "r"(b[1]));
}
__device__ __forceinline__ void cpa16(uint32_t dst, const void* src, unsigned n) {
    asm volatile("cp.async.cg.shared.global [%0], [%1], 16, %2;"
                 :: "r"(dst), "l"(src), "r"(n));
}
#define CP_COMMIT() asm volatile("cp.async.commit_group;" ::: "memory")
#define CP_WAIT2()  asm volatile("cp.async.wait_group 2;"  ::: "memory")
#define CP_WAIT1()  asm volatile("cp.async.wait_group 1;"  ::: "memory")
#define CP_WAIT0()  asm volatile("cp.async.wait_group 0;"  ::: "memory")

// ---------------------------------------------------------------------------
// Standalone fp16 GEMM (exact R9 config — best measured)
// ---------------------------------------------------------------------------
__global__ void __launch_bounds__(256, 2)
gemm_f16(const __half* __restrict__ A, int lda,
         const __half* __restrict__ B, int ldb,
         const float* __restrict__ bias,
         const __half* __restrict__ AD, int ldad,
         float* __restrict__ Cf, __half* __restrict__ Ch,
         int ldc, int N, int K, int epi)
{
    extern __shared__ __align__(16) char smem[];
    const uint32_t sb = smem_u32(smem);

    const int tid    = threadIdx.x;
    const int lane   = tid & 31;
    const int wid    = tid >> 5;
    const int warpM  = wid >> 2;
    const int warpN  = wid & 3;
    const int blockM = blockIdx.y * 128;
    const int blockN = blockIdx.x * 128;

    const int r0 = tid >> 2, q0 = tid & 3;
    const __half* pAa = A + (size_t)(blockM + r0) * lda + q0 * 8;
    const __half* pAb = pAa + (size_t)64 * lda;
    const int nGa = blockN + r0, nGb = nGa + 64;
    const unsigned szBa = (nGa < N) ? 16u : 0u;
    const unsigned szBb = (nGb < N) ? 16u : 0u;
    const __half* pBa = B + (size_t)(nGa < N ? nGa : 0) * ldb + q0 * 8;
    const __half* pBb = B + (size_t)(nGb < N ? nGb : 0) * ldb + q0 * 8;
    const uint32_t dRa = (uint32_t)(r0 * G_RSTR + q0 * 16);
    const uint32_t dRb = dRa + 64 * G_RSTR;

    const uint32_t aOffB = (uint32_t)((warpM * 64 + (lane & 15)) * G_RSTR + (lane >> 4) * 16);
    const uint32_t bOffB = (uint32_t)((warpN * 32 + (lane & 7)) * G_RSTR + ((lane >> 3) & 1) * 16);

    float acc[4][4][4];
    #pragma unroll
    for (int mt = 0; mt < 4; ++mt)
        #pragma unroll
        for (int nt = 0; nt < 4; ++nt)
            #pragma unroll
            for (int i = 0; i < 4; ++i) acc[mt][nt][i] = 0.0f;

    const int nk = K / G_KC;

    auto stage_copy = [&](int slot, int k0) {
        const uint32_t so = sb + (uint32_t)(slot * G_STG);
        cpa16(so + dRa,          pAa + k0, 16u);
        cpa16(so + dRb,          pAb + k0, 16u);
        cpa16(so + G_OFFB + dRa, pBa + k0, szBa);
        cpa16(so + G_OFFB + dRb, pBb + k0, szBb);
    };

    stage_copy(0, 0);                     CP_COMMIT();
    if (nk > 1) stage_copy(1, G_KC);      CP_COMMIT();
    if (nk > 2) stage_copy(2, 2 * G_KC);  CP_COMMIT();

    for (int kt = 0; kt < nk; ++kt) {
        CP_WAIT2();
        __syncthreads();

        if (kt + 3 < nk) stage_copy((kt + 3) & 3, (kt + 3) * G_KC);
        CP_COMMIT();

        const uint32_t so = sb + (uint32_t)((kt & 3) * G_STG);
        #pragma unroll
        for (int ks = 0; ks < 2; ++ks) {
            unsigned Af[4][4];
            #pragma unroll
            for (int mt = 0; mt < 4; ++mt)
                ldm4(Af[mt], so + aOffB + (uint32_t)(mt * 16 * G_RSTR + ks * 32));
            #pragma unroll
            for (int nt = 0; nt < 4; ++nt) {
                unsigned Bf[2];
                ldm2(Bf, so + G_OFFB + bOffB + (uint32_t)(nt * 8 * G_RSTR + ks * 32));
                #pragma unroll
                for (int mt = 0; mt < 4; ++mt)
                    mma_f16(acc[mt][nt], Af[mt], Bf);
            }
        }
    }
    CP_WAIT0();

    const int g = lane >> 2, q = lane & 3;
    #pragma unroll
    for (int mt = 0; mt < 4; ++mt) {
        #pragma unroll
        for (int nt = 0; nt < 4; ++nt) {
            const int row0 = blockM + warpM * 64 + mt * 16 + g;
            const int col  = blockN + warpN * 32 + nt * 8 + q * 2;
            const bool c0 = col < N, c1 = (col + 1) < N;
            const float b0v = c0 ? bias[col] : 0.0f;
            const float b1v = c1 ? bias[col + 1] : 0.0f;
            #pragma unroll
            for (int rr = 0; rr < 2; ++rr) {
                const int r = row0 + rr * 8;
                float v0 = acc[mt][nt][rr * 2 + 0] + b0v;
                float v1 = acc[mt][nt][rr * 2 + 1] + b1v;
                if (AD) {
                    const size_t o = (size_t)r * ldad + col;
                    if (c0) v0 += __half2float(AD[o]);
                    if (c1) v1 += __half2float(AD[o + 1]);
                }
                if (epi == EPI_RELU)      { v0 = fmaxf(v0, 0.0f); v1 = fmaxf(v1, 0.0f); }
                else if (epi == EPI_TANH) { v0 = tanh_fast(v0);   v1 = tanh_fast(v1);   }
                const size_t oc = (size_t)r * ldc + col;
                if (Cf) {
                    if (c0) Cf[oc]     = v0;
                    if (c1) Cf[oc + 1] = v1;
                } else {
                    if (c0 && c1) {
                        *(__half2*)(Ch + oc) = __floats2half2_rn(v0, v1);
                    } else if (c0) {
                        Ch[oc] = __float2half_rn(v0);
                    }
                }
            }
        }
    }
}

// ---------------------------------------------------------------------------
// Fused residual block: h' = tanh( tanh(h@W1^T + b1) @ W2^T + b2 + h )
// CTA = 64 batch rows, full N=1024. 512 threads (16 warps).
// Phase 1: u -> SMEM (fp16). Phase 2: A from SMEM, B pipelined.
// Warp org: pairI = wid>>3 selects slab parity; 8 warps (2M x 4N) of 32x32.
// ---------------------------------------------------------------------------
__global__ void __launch_bounds__(512, 1)
resblock(const __half* __restrict__ Hin, const __half* __restrict__ W1,
         const float* __restrict__ b1, const __half* __restrict__ W2,
         const float* __restrict__ b2, __half* __restrict__ Hout)
{
    extern __shared__ __align__(16) char smem[];
    const uint32_t sb = smem_u32(smem);

    const int tid   = threadIdx.x;
    const int lane  = tid & 31;
    const int wid   = tid >> 5;
    const int pairI = wid >> 3;          // 0..1: which slab of the pair
    const int w8    = wid & 7;
    const int warpM = w8 >> 2;           // 0..1: 32-row half
    const int warpN = w8 & 3;            // 0..3: 32-col quarter of 128-col slab
    const int blockM = blockIdx.x * 64;

    // A-fragment base (phase1, stage memory; stride G-style 80B)
    const uint32_t aOff1 = (uint32_t)((warpM * 32 + (lane & 15)) * 80 + (lane >> 4) * 16);
    // B-fragment base: lane mapping so reg pairs are (n0-7),(n8-15)
    const uint32_t bLane = (uint32_t)(((lane >> 4) * 8 + (lane & 7)) * 80 + ((lane >> 3) & 1) * 16);
    const uint32_t bOff  = (uint32_t)(R_PHB + (pairI * 128 + warpN * 32) * 80) + bLane;
    // A-fragment base (phase2, u in SMEM; stride R_USTR)
    const uint32_t uOffA = (uint32_t)(R_UOFF + (warpM * 32 + (lane & 15)) * R_USTR + (lane >> 4) * 16);

    const int g = lane >> 2, q = lane & 3;

    // ---- stage copy lambdas ----
    auto copyAB = [&](int slot, int k0, int slab2, const __half* W) {
        const uint32_t so = sb + (uint32_t)(slot * R_STG);
        #pragma unroll
        for (int j = 0; j < 3; ++j) {
            const int u = tid + 512 * j;
            if (u < 256) {                       // A: h rows
                const int r = u >> 2, qq = u & 3;
                cpa16(so + (uint32_t)(r * 80 + qq * 16),
                      Hin + (size_t)(blockM + r) * HDIM + k0 + qq * 8, 16u);
            } else if (u < 1280) {               // B: 2 slabs x 128 rows
                const int ub = u - 256;
                const int r = ub >> 2, qq = ub & 3;
                const int n = (slab2 + (r >> 7)) * 128 + (r & 127);
                cpa16(so + (uint32_t)(R_PHB + r * 80 + qq * 16),
                      W + (size_t)n * HDIM + k0 + qq * 8, 16u);
            }
        }
    };
    auto copyB = [&](int slot, int k0, int slab2, const __half* W) {
        const uint32_t so = sb + (uint32_t)(slot * R_STG);
        #pragma unroll
        for (int j = 0; j < 2; ++j) {
            const int ub = tid + 512 * j;        // 0..1023
            const int r = ub >> 2, qq = ub & 3;
            const int n = (slab2 + (r >> 7)) * 128 + (r & 127);
            cpa16(so + (uint32_t)(R_PHB + r * 80 + qq * 16),
                  W + (size_t)n * HDIM + k0 + qq * 8, 16u);
        }
    };

    // ================= Phase 1: u = tanh(h @ W1^T + b1) -> SMEM ============
    for (int slab2 = 0; slab2 < 8; slab2 += 2) {
        float acc[2][4][4];
        #pragma unroll
        for (int mt = 0; mt < 2; ++mt)
            #pragma unroll
            for (int j = 0; j < 4; ++j)
                #pragma unroll
                for (int i = 0; i < 4; ++i) acc[mt][j][i] = 0.0f;

        copyAB(0, 0, slab2, W1);  CP_COMMIT();
        copyAB(1, 32, slab2, W1); CP_COMMIT();

        for (int kt = 0; kt < 32; ++kt) {
            CP_WAIT1();
            __syncthreads();
            if (kt + 2 < 32) copyAB((kt + 2) % 3, (kt + 2) * 32, slab2, W1);
            CP_COMMIT();

            const uint32_t so = sb + (uint32_t)((kt % 3) * R_STG);
            #pragma unroll
            for (int ks = 0; ks < 2; ++ks) {
                unsigned Af[2][4], Bf[2][4];
                ldm4(Af[0], so + aOff1 + ks * 32);
                ldm4(Af[1], so + aOff1 + 16 * 80 + ks * 32);
                ldm4(Bf[0], so + bOff + ks * 32);
                ldm4(Bf[1], so + bOff + 16 * 80 + ks * 32);
                #pragma unroll
                for (int nt = 0; nt < 2; ++nt)
                    #pragma unroll
                    for (int mt = 0; mt < 2; ++mt) {
                        mma_f16(acc[mt][2 * nt + 0], Af[mt], &Bf[nt][0]);
                        mma_f16(acc[mt][2 * nt + 1], Af[mt], &Bf[nt][2]);
                    }
            }
        }

        // epilogue: tanh -> u in SMEM
        const int slab = slab2 + pairI;
        #pragma unroll
        for (int mt = 0; mt < 2; ++mt) {
            #pragma unroll
            for (int j = 0; j < 4; ++j) {
                const int col = slab * 128 + warpN * 32 + (j >> 1) * 16 + (j & 1) * 8 + q * 2;
                const float b0v = b1[col], b1v = b1[col + 1];
                #pragma unroll
                for (int rr = 0; rr < 2; ++rr) {
                    const int row = warpM * 32 + mt * 16 + g + rr * 8;
                    float v0 = tanh_fast(acc[mt][j][rr * 2 + 0] + b0v);
                    float v1 = tanh_fast(acc[mt][j][rr * 2 + 1] + b1v);
                    *(__half2*)(smem + R_UOFF + row * R_USTR + col * 2) =
                        __floats2half2_rn(v0, v1);
                }
            }
        }
        __syncthreads();   // u writes + stage reads complete before reuse
    }

    // ================= Phase 2: h' = tanh(u @ W2^T + b2 + h) ===============
    for (int slab2 = 0; slab2 < 8; slab2 += 2) {
        float acc[2][4][4];
        #pragma unroll
        for (int mt = 0; mt < 2; ++mt)
            #pragma unroll
            for (int j = 0; j < 4; ++j)
                #pragma unroll
                for (int i = 0; i < 4; ++i) acc[mt][j][i] = 0.0f;

        copyB(0, 0, slab2, W2);  CP_COMMIT();
        copyB(1, 32, slab2, W2); CP_COMMIT();

        for (int kt = 0; kt < 32; ++kt) {
            CP_WAIT1();
            __syncthreads();
            if (kt + 2 < 32) copyB((kt + 2) % 3, (kt + 2) * 32, slab2, W2);
            CP_COMMIT();

            const uint32_t so = sb + (uint32_t)((kt % 3) * R_STG);
            #pragma unroll
            for (int ks = 0; ks < 2; ++ks) {
                unsigned Af[2][4], Bf[2][4];
                const uint32_t ku = (uint32_t)(kt * 64 + ks * 32);
                ldm4(Af[0], sb + uOffA + ku);
                ldm4(Af[1], sb + uOffA + 16 * R_USTR + ku);
                ldm4(Bf[0], so + bOff + ks * 32);
                ldm4(Bf[1], so + bOff + 16 * 80 + ks * 32);
                #pragma unroll
                for (int nt = 0; nt < 2; ++nt)
                    #pragma unroll
                    for (int mt = 0; mt < 2; ++mt) {
                        mma_f16(acc[mt][2 * nt + 0], Af[mt], &Bf[nt][0]);
                        mma_f16(acc[mt][2 * nt + 1], Af[mt], &Bf[nt][2]);
                    }
            }
        }

        // epilogue: + b2 + h residual, tanh -> global
        const int slab = slab2 + pairI;
        #pragma unroll
        for (int mt = 0; mt < 2; ++mt) {
            #pragma unroll
            for (int j = 0; j < 4; ++j) {
                const int col = slab * 128 + warpN * 32 + (j >> 1) * 16 + (j & 1) * 8 + q * 2;
                const float b0v = b2[col], b1v = b2[col + 1];
                #pragma unroll
                for (int rr = 0; rr < 2; ++rr) {
                    const int row = warpM * 32 + mt * 16 + g + rr * 8;
                    const size_t o = (size_t)(blockM + row) * HDIM + col;
                    const __half2 hres = *(const __half2*)(Hin + o);
                    float v0 = tanh_fast(acc[mt][j][rr * 2 + 0] + b0v + __half2float(__low2half(hres)));
                    float v1 = tanh_fast(acc[mt][j][rr * 2 + 1] + b1v + __half2float(__high2half(hres)));
                    *(__half2*)(Hout + o) = __floats2half2_rn(v0, v1);
                }
            }
        }
        __syncthreads();
    }
}

// ---------------------------------------------------------------------------
// Prologue: fp16 conversions
// ---------------------------------------------------------------------------
#define N_W1 (RB*HDIM*HDIM)
#define N_W2 (RB*HDIM*HDIM)
#define N_WF (SDIM*HDIM)
#define N_TT (ADIM*ADIM)
#define N_ALL (N_W1 + N_W2 + N_WF + N_TT + N_TT)

__global__ void conv_all_kernel(const float* __restrict__ rW1, const float* __restrict__ rW2,
                                const float* __restrict__ Wf,  const float* __restrict__ ta_in_w,
                                const float* __restrict__ ta_out_w)
{
    const int i4 = blockIdx.x * blockDim.x + threadIdx.x;
    const long long i = (long long)i4 * 4;
    if (i >= N_ALL) return;
    const float* src; __half* dst; long long off;
    if (i < N_W1)                           { src = rW1;                         dst = g_W1; off = i; }
    else if (i < N_W1 + N_W2)               { src = rW2;                         dst = g_W2; off = i - N_W1; }
    else if (i < N_W1 + N_W2 + N_WF)        { src = Wf;                          dst = g_Wf; off = i - N_W1 - N_W2; }
    else if (i < N_W1 + N_W2 + N_WF + N_TT) { src = ta_in_w + 2 * ADIM * ADIM;   dst = g_TI; off = i - N_W1 - N_W2 - N_WF; }
    else                                    { src = ta_out_w;                    dst = g_TO; off = i - N_W1 - N_W2 - N_WF - N_TT; }
    float4 v = *(const float4*)(src + off);
    __half2* d = (__half2*)(dst + off);
    d[0] = __floats2half2_rn(v.x, v.y);
    d[1] = __floats2half2_rn(v.z, v.w);
}

#define N_CW0 (HDIM*KX)
__global__ void prep_kernel(const float* __restrict__ W0,
                            const float* __restrict__ state, const float* __restrict__ t)
{
    int i = blockIdx.x * blockDim.x + threadIdx.x;
    if (i < N_CW0) {
        int row = i / KX, c = i % KX;
        float v = (c < SDIM + 2) ? W0[row * (SDIM + 2) + c] : 0.0f;
        g_W0[i] = __float2half_rn(v);
        return;
    }
    i -= N_CW0;
    if (i >= BATCH * KX) return;
    int b = i / KX, c = i % KX;
    float v;
    if (c < SDIM) v = state[b * SDIM + c];
    else if (c == SDIM)     { float ang = t[0] * 0.26179938779914943654f; v = sinf(ang); }
    else if (c == SDIM + 1) { float ang = t[0] * 0.26179938779914943654f; v = cosf(ang); }
    else v = 0.0f;
    g_x[i] = __float2half_rn(v);
}

// ---------------------------------------------------------------------------
// Tiny loc path (exact fp32)
// ---------------------------------------------------------------------------
__global__ void loc_kernel(const float* __restrict__ state,
                           const float* __restrict__ loc_proj_w, const float* __restrict__ loc_proj_b,
                           const float* __restrict__ lp_in_w,    const float* __restrict__ lp_in_b,
                           const float* __restrict__ lp_out_w,   const float* __restrict__ lp_out_b,
                           const float* __restrict__ loc_back_w, const float* __restrict__ loc_back_b,
                           float* __restrict__ dloc)
{
    int b = blockIdx.x * blockDim.x + threadIdx.x;
    if (b >= BATCH) return;
    float loc[ZDIM];
    #pragma unroll
    for (int z = 0; z < ZDIM; ++z) loc[z] = state[b * SDIM + ADIM + z];
    float lp[EDIM];
    #pragma unroll
    for (int e = 0; e < EDIM; ++e) {
        float s = loc_proj_b[e];
        #pragma unroll
        for (int z = 0; z < ZDIM; ++z) s += loc_proj_w[e * ZDIM + z] * loc[z];
        lp[e] = s;
    }
    float v[EDIM];
    #pragma unroll
    for (int e = 0; e < EDIM; ++e) {
        float s = lp_in_b[2 * EDIM + e];
        #pragma unroll
        for (int j = 0; j < EDIM; ++j) s += lp_in_w[(2 * EDIM + e) * EDIM + j] * lp[j];
        v[e] = s;
    }
    float d[EDIM];
    #pragma unroll
    for (int e = 0; e < EDIM; ++e) {
        float s = lp_out_b[e];
        #pragma unroll
        for (int j = 0; j < EDIM; ++j) s += lp_out_w[e * EDIM + j] * v[j];
        d[e] = s - lp[e];
    }
    #pragma unroll
    for (int z = 0; z < ZDIM; ++z) {
        float s = loc_back_b[z];
        #pragma unroll
        for (int e = 0; e < EDIM; ++e) s += loc_back_w[z * EDIM + e] * d[e];
        dloc[b * ZDIM + z] = s;
    }
}

__global__ void combine_kernel(float* __restrict__ out,
                               const float* __restrict__ state,
                               const float* __restrict__ dh,
                               const float* __restrict__ dloc)
{
    int i = blockIdx.x * blockDim.x + threadIdx.x;
    if (i >= BATCH * SDIM) return;
    int b = i / SDIM, j = i % SDIM;
    float o = out[i];
    if (j < ADIM)              o += 0.1f * (dh[b * ADIM + j] - state[i]);
    else if (j < ADIM + ZDIM)  o += 0.1f * dloc[b * ZDIM + (j - ADIM)];
    out[i] = o;
}

// ---------------------------------------------------------------------------
// Launch
// ---------------------------------------------------------------------------
extern "C" void kernel_launch(void* const* d_in, const int* in_sizes, int n_in,
                              void* d_out, int out_size)
{
    const float* t          = (const float*)d_in[0];
    const float* state      = (const float*)d_in[1];
    const float* W0         = (const float*)d_in[2];
    const float* b0         = (const float*)d_in[3];
    const float* rW1        = (const float*)d_in[4];
    const float* rb1        = (const float*)d_in[5];
    const float* rW2        = (const float*)d_in[6];
    const float* rb2        = (const float*)d_in[7];
    const float* Wf         = (const float*)d_in[8];
    const float* bf_        = (const float*)d_in[9];
    const float* lp_in_w    = (const float*)d_in[10];
    const float* lp_in_b    = (const float*)d_in[11];
    const float* lp_out_w   = (const float*)d_in[12];
    const float* lp_out_b   = (const float*)d_in[13];
    const float* ta_in_w    = (const float*)d_in[14];
    const float* ta_in_b    = (const float*)d_in[15];
    const float* ta_out_w   = (const float*)d_in[16];
    const float* ta_out_b   = (const float*)d_in[17];
    const float* loc_proj_w = (const float*)d_in[18];
    const float* loc_proj_b = (const float*)d_in[19];
    const float* loc_back_w = (const float*)d_in[20];
    const float* loc_back_b = (const float*)d_in[21];
    float* out = (float*)d_out;

    __half *x, *hA, *hB, *v;
    float *dh, *dloc;
    __half *W0h, *W1h, *W2h, *Wfh, *TIh, *TOh;
    cudaGetSymbolAddress((void**)&x,  g_x);
    cudaGetSymbolAddress((void**)&hA, g_hA);
    cudaGetSymbolAddress((void**)&hB, g_hB);
    cudaGetSymbolAddress((void**)&v,  g_v);
    cudaGetSymbolAddress((void**)&dh, g_dh);
    cudaGetSymbolAddress((void**)&dloc, g_dloc);
    cudaGetSymbolAddress((void**)&W0h, g_W0);
    cudaGetSymbolAddress((void**)&W1h, g_W1);
    cudaGetSymbolAddress((void**)&W2h, g_W2);
    cudaGetSymbolAddress((void**)&Wfh, g_Wf);
    cudaGetSymbolAddress((void**)&TIh, g_TI);
    cudaGetSymbolAddress((void**)&TOh, g_TO);

    cudaFuncSetAttribute(gemm_f16, cudaFuncAttributeMaxDynamicSharedMemorySize, G_SMEM);
    cudaFuncSetAttribute(resblock, cudaFuncAttributeMaxDynamicSharedMemorySize, R_SMEM);

    // --- prologue (2 launches) ---
    conv_all_kernel<<<CDIV(N_ALL / 4, 256), 256>>>(rW1, rW2, Wf, ta_in_w, ta_out_w);
    prep_kernel<<<CDIV(N_CW0 + BATCH * KX, 256), 256>>>(W0, state, t);

    // --- main chain ---
    dim3 blk(256);
    dim3 gH(HDIM / 128, BATCH / 128);           // (8, 64)

    // h = relu(x @ W0^T + b0)
    gemm_f16<<<gH, blk, G_SMEM>>>(x, KX, W0h, KX, b0, nullptr, 0,
                                  nullptr, hA, HDIM, HDIM, KX, EPI_RELU);

    __half *hc = hA, *hn = hB;
    for (int i = 0; i < RB; ++i) {
        resblock<<<BATCH / 64, 512, R_SMEM>>>(hc,
                                              W1h + (size_t)i * HDIM * HDIM, rb1 + i * HDIM,
                                              W2h + (size_t)i * HDIM * HDIM, rb2 + i * HDIM,
                                              hn);
        __half* tmp = hc; hc = hn; hn = tmp;
    }

    // core = h @ Wf^T + bf -> f32 out
    dim3 gF(CDIV(SDIM, 128), BATCH / 128);      // (3, 64)
    gemm_f16<<<gF, blk, G_SMEM>>>(hc, HDIM, Wfh, HDIM, bf_, nullptr, 0,
                                  out, nullptr, SDIM, SDIM, HDIM, EPI_NONE);

    // --- independent side path (h_part = first 256 cols of x) ---
    dim3 gT(ADIM / 128, BATCH / 128);           // (2, 64)
    gemm_f16<<<gT, blk, G_SMEM>>>(x, KX, TIh, ADIM, ta_in_b + 2 * ADIM, nullptr, 0,
                                  nullptr, v, ADIM, ADIM, ADIM, EPI_NONE);
    gemm_f16<<<gT, blk, G_SMEM>>>(v, ADIM, TOh, ADIM, ta_out_b, nullptr, 0,
                                  dh, nullptr, ADIM, ADIM, ADIM, EPI_NONE);
    loc_kernel<<<CDIV(BATCH, 256), 256>>>(state, loc_proj_w, loc_proj_b,
                                          lp_in_w, lp_in_b, lp_out_w, lp_out_b,
                                          loc_back_w, loc_back_b, dloc);

    combine_kernel<<<CDIV(BATCH * SDIM, 256), 256>>>(out, state, dh, dloc);
}

// round 15
// speedup vs baseline: 1.7284x; 1.7284x over previous
#include <cuda_runtime.h>
#include <cuda_fp16.h>
#include <cstdint>
#include <math.h>

#define BATCH 8192
#define SDIM  268
#define HDIM  1024
#define RB    8
#define ADIM  256
#define ZDIM  8
#define EDIM  4
#define KX    288   /* 270 padded to multiple of 32 */

#define CDIV(a,b) (((a)+(b)-1)/(b))
#define EPI_NONE 0
#define EPI_RELU 1
#define EPI_TANH 2

// GEMM: CTA 256x128, 16 warps (4M x 4N), warp tile 64x32, K chunk 32
#define KC     32
#define RSTR   80               /* 64B data + 16B pad per row */
#define OFF_B  20480            /* A level = 256*80 */
#define STG_SZ 30720            /* A(256 rows) + B(128 rows) */
#define NSTAGE 4
#define SMEM_DYN (NSTAGE*STG_SZ)   /* 122880 B */

// ---------------------------------------------------------------------------
// Scratch (static __device__ arrays; no allocation anywhere)
// ---------------------------------------------------------------------------
__device__ __align__(16) __half g_x [BATCH*KX];
__device__ __align__(16) __half g_hA[BATCH*HDIM];
__device__ __align__(16) __half g_hB[BATCH*HDIM];
__device__ __align__(16) __half g_u [BATCH*HDIM];
__device__ __align__(16) __half g_v [BATCH*ADIM];
__device__ __align__(16) float  g_dh[BATCH*ADIM];
__device__ __align__(16) float  g_dloc[BATCH*ZDIM];

__device__ __align__(16) __half g_W0[HDIM*KX];
__device__ __align__(16) __half g_W1[RB*HDIM*HDIM];
__device__ __align__(16) __half g_W2[RB*HDIM*HDIM];
__device__ __align__(16) __half g_Wf[SDIM*HDIM];
__device__ __align__(16) __half g_TI[ADIM*ADIM];
__device__ __align__(16) __half g_TO[ADIM*ADIM];

// ---------------------------------------------------------------------------
// Helpers
// ---------------------------------------------------------------------------
__device__ __forceinline__ float tanh_fast(float x) {
    float e = __expf(2.0f * x);
    return 1.0f - __fdividef(2.0f, e + 1.0f);   // NaN-safe
}
__device__ __forceinline__ uint32_t smem_u32(const void* p) {
    uint32_t a;
    asm("{ .reg .u64 t; cvta.to.shared.u64 t, %1; cvt.u32.u64 %0, t; }" : "=r"(a) : "l"(p));
    return a;
}
__device__ __forceinline__ void ldm4(unsigned r[4], uint32_t addr) {
    asm volatile("ldmatrix.sync.aligned.m8n8.x4.shared.b16 {%0,%1,%2,%3}, [%4];"
                 : "=r"(r[0]), "=r"(r[1]), "=r"(r[2]), "=r"(r[3]) : "r"(addr));
}
__device__ __forceinline__ void ldm2(unsigned r[2], uint32_t addr) {
    asm volatile("ldmatrix.sync.aligned.m8n8.x2.shared.b16 {%0,%1}, [%2];"
                 : "=r"(r[0]), "=r"(r[1]) : "r"(addr));
}
__device__ __forceinline__ void mma_f16(float c[4], const unsigned a[4], const unsigned b[2]) {
    asm volatile(
        "mma.sync.aligned.m16n8k16.row.col.f32.f16.f16.f32 "
        "{%0,%1,%2,%3}, {%4,%5,%6,%7}, {%8,%9}, {%0,%1,%2,%3};"
        : "+f"(c[0]), "+f"(c[1]), "+f"(c[2]), "+f"(c[3])
        : "r"(a[0]), "r"(a[1]), "r"(a[2]), "r"(a[3]), "r"(b[0]), "r"(b[1]));
}
__device__ __forceinline__ void cpa16(uint32_t dst, const void* src, unsigned n) {
    asm volatile("cp.async.cg.shared.global [%0], [%1], 16, %2;"
                 :: "r"(dst), "l"(src), "r"(n));
}
#define CP_COMMIT() asm volatile("cp.async.commit_group;" ::: "memory")
#define CP_WAIT2()  asm volatile("cp.async.wait_group 2;"  ::: "memory")
#define CP_WAIT0()  asm volatile("cp.async.wait_group 0;"  ::: "memory")

// ---------------------------------------------------------------------------
// fp16 GEMM: C(MxN) = act( A(MxK) @ B^T + bias [+ AD] )
// CTA 256x128, 512 threads, 16 warps (4M x 4N), warp tile 64x32 (R9 engine),
// KC=32, 4-stage cp.async, 1 CTA/SM (16 warps/SM, same as R9).
// ---------------------------------------------------------------------------
__global__ void __launch_bounds__(512, 1)
gemm_f16(const __half* __restrict__ A, int lda,
         const __half* __restrict__ B, int ldb,
         const float* __restrict__ bias,
         const __half* __restrict__ AD, int ldad,
         float* __restrict__ Cf, __half* __restrict__ Ch,
         int ldc, int N, int K, int epi)
{
    extern __shared__ __align__(16) char smem[];
    const uint32_t sb = smem_u32(smem);

    const int tid    = threadIdx.x;
    const int lane   = tid & 31;
    const int wid    = tid >> 5;
    const int warpM  = wid >> 2;        // 0..3
    const int warpN  = wid & 3;         // 0..3
    const int blockM = blockIdx.y * 256;
    const int blockN = blockIdx.x * 128;

    // ---- staging: 1536 16B-units per stage (A 1024, B 512); 3 per thread ----
    // unit u: A if u<1024 (row=u>>2, q=u&3), else B (row=(u-1024)>>2, q=..&3)
    const int uA = tid;                  // j=0,1 -> A units (tid, tid+512)
    const int uB = tid;                  // j=2   -> B unit tid
    const int rA0 = uA >> 2,           qA0 = uA & 3;
    const int rA1 = (uA + 512) >> 2,   qA1 = (uA + 512) & 3;
    const int rB  = uB >> 2,           qB  = uB & 3;

    const __half* pA0 = A + (size_t)(blockM + rA0) * lda + qA0 * 8;
    const __half* pA1 = A + (size_t)(blockM + rA1) * lda + qA1 * 8;
    const int nG = blockN + rB;
    const unsigned szB = (nG < N) ? 16u : 0u;
    const __half* pB = B + (size_t)(nG < N ? nG : 0) * ldb + qB * 8;

    const uint32_t dA0 = (uint32_t)(rA0 * RSTR + qA0 * 16);
    const uint32_t dA1 = (uint32_t)(rA1 * RSTR + qA1 * 16);
    const uint32_t dB  = (uint32_t)(OFF_B + rB * RSTR + qB * 16);

    // ldmatrix bases within a stage (identical shape to R9)
    const uint32_t aOffB = (uint32_t)((warpM * 64 + (lane & 15)) * RSTR + (lane >> 4) * 16);
    const uint32_t bOffB = (uint32_t)((warpN * 32 + (lane & 7)) * RSTR + ((lane >> 3) & 1) * 16);

    float acc[4][4][4];
    #pragma unroll
    for (int mt = 0; mt < 4; ++mt)
        #pragma unroll
        for (int nt = 0; nt < 4; ++nt)
            #pragma unroll
            for (int i = 0; i < 4; ++i) acc[mt][nt][i] = 0.0f;

    const int nk = K / KC;

    auto stage_copy = [&](int slot, int k0) {
        const uint32_t so = sb + (uint32_t)(slot * STG_SZ);
        cpa16(so + dA0, pA0 + k0, 16u);
        cpa16(so + dA1, pA1 + k0, 16u);
        cpa16(so + dB,  pB  + k0, szB);
    };

    stage_copy(0, 0);                  CP_COMMIT();
    if (nk > 1) stage_copy(1, KC);     CP_COMMIT();
    if (nk > 2) stage_copy(2, 2 * KC); CP_COMMIT();

    for (int kt = 0; kt < nk; ++kt) {
        CP_WAIT2();
        __syncthreads();

        if (kt + 3 < nk) stage_copy((kt + 3) & 3, (kt + 3) * KC);
        CP_COMMIT();

        const uint32_t so = sb + (uint32_t)((kt & 3) * STG_SZ);
        #pragma unroll
        for (int ks = 0; ks < 2; ++ks) {
            unsigned Af[4][4];
            #pragma unroll
            for (int mt = 0; mt < 4; ++mt)
                ldm4(Af[mt], so + aOffB + (uint32_t)(mt * 16 * RSTR + ks * 32));
            #pragma unroll
            for (int nt = 0; nt < 4; ++nt) {
                unsigned Bf[2];
                ldm2(Bf, so + OFF_B + bOffB + (uint32_t)(nt * 8 * RSTR + ks * 32));
                #pragma unroll
                for (int mt = 0; mt < 4; ++mt)
                    mma_f16(acc[mt][nt], Af[mt], Bf);
            }
        }
    }
    CP_WAIT0();

    // ---- epilogue ----
    const int g = lane >> 2, q = lane & 3;
    #pragma unroll
    for (int mt = 0; mt < 4; ++mt) {
        #pragma unroll
        for (int nt = 0; nt < 4; ++nt) {
            const int row0 = blockM + warpM * 64 + mt * 16 + g;
            const int col  = blockN + warpN * 32 + nt * 8 + q * 2;
            const bool c0 = col < N, c1 = (col + 1) < N;
            const float b0v = c0 ? bias[col] : 0.0f;
            const float b1v = c1 ? bias[col + 1] : 0.0f;
            #pragma unroll
            for (int rr = 0; rr < 2; ++rr) {
                const int r = row0 + rr * 8;
                float v0 = acc[mt][nt][rr * 2 + 0] + b0v;
                float v1 = acc[mt][nt][rr * 2 + 1] + b1v;
                if (AD) {
                    const size_t o = (size_t)r * ldad + col;
                    if (c0) v0 += __half2float(AD[o]);
                    if (c1) v1 += __half2float(AD[o + 1]);
                }
                if (epi == EPI_RELU)      { v0 = fmaxf(v0, 0.0f); v1 = fmaxf(v1, 0.0f); }
                else if (epi == EPI_TANH) { v0 = tanh_fast(v0);   v1 = tanh_fast(v1);   }
                const size_t oc = (size_t)r * ldc + col;
                if (Cf) {
                    if (c0) Cf[oc]     = v0;
                    if (c1) Cf[oc + 1] = v1;
                } else {
                    if (c0 && c1) {
                        *(__half2*)(Ch + oc) = __floats2half2_rn(v0, v1);
                    } else if (c0) {
                        Ch[oc] = __float2half_rn(v0);
                    }
                }
            }
        }
    }
}

// ---------------------------------------------------------------------------
// Prologue: fp16 conversions
// ---------------------------------------------------------------------------
#define N_W1 (RB*HDIM*HDIM)
#define N_W2 (RB*HDIM*HDIM)
#define N_WF (SDIM*HDIM)
#define N_TT (ADIM*ADIM)
#define N_ALL (N_W1 + N_W2 + N_WF + N_TT + N_TT)

__global__ void conv_all_kernel(const float* __restrict__ rW1, const float* __restrict__ rW2,
                                const float* __restrict__ Wf,  const float* __restrict__ ta_in_w,
                                const float* __restrict__ ta_out_w)
{
    const int i4 = blockIdx.x * blockDim.x + threadIdx.x;
    const long long i = (long long)i4 * 4;
    if (i >= N_ALL) return;
    const float* src; __half* dst; long long off;
    if (i < N_W1)                           { src = rW1;                         dst = g_W1; off = i; }
    else if (i < N_W1 + N_W2)               { src = rW2;                         dst = g_W2; off = i - N_W1; }
    else if (i < N_W1 + N_W2 + N_WF)        { src = Wf;                          dst = g_Wf; off = i - N_W1 - N_W2; }
    else if (i < N_W1 + N_W2 + N_WF + N_TT) { src = ta_in_w + 2 * ADIM * ADIM;   dst = g_TI; off = i - N_W1 - N_W2 - N_WF; }
    else                                    { src = ta_out_w;                    dst = g_TO; off = i - N_W1 - N_W2 - N_WF - N_TT; }
    float4 v = *(const float4*)(src + off);
    __half2* d = (__half2*)(dst + off);
    d[0] = __floats2half2_rn(v.x, v.y);
    d[1] = __floats2half2_rn(v.z, v.w);
}

#define N_CW0 (HDIM*KX)
__global__ void prep_kernel(const float* __restrict__ W0,
                            const float* __restrict__ state, const float* __restrict__ t)
{
    int i = blockIdx.x * blockDim.x + threadIdx.x;
    if (i < N_CW0) {
        int row = i / KX, c = i % KX;
        float v = (c < SDIM + 2) ? W0[row * (SDIM + 2) + c] : 0.0f;
        g_W0[i] = __float2half_rn(v);
        return;
    }
    i -= N_CW0;
    if (i >= BATCH * KX) return;
    int b = i / KX, c = i % KX;
    float v;
    if (c < SDIM) v = state[b * SDIM + c];
    else if (c == SDIM)     { float ang = t[0] * 0.26179938779914943654f; v = sinf(ang); }
    else if (c == SDIM + 1) { float ang = t[0] * 0.26179938779914943654f; v = cosf(ang); }
    else v = 0.0f;
    g_x[i] = __float2half_rn(v);
}

// ---------------------------------------------------------------------------
// Tiny loc path (exact fp32)
// ---------------------------------------------------------------------------
__global__ void loc_kernel(const float* __restrict__ state,
                           const float* __restrict__ loc_proj_w, const float* __restrict__ loc_proj_b,
                           const float* __restrict__ lp_in_w,    const float* __restrict__ lp_in_b,
                           const float* __restrict__ lp_out_w,   const float* __restrict__ lp_out_b,
                           const float* __restrict__ loc_back_w, const float* __restrict__ loc_back_b,
                           float* __restrict__ dloc)
{
    int b = blockIdx.x * blockDim.x + threadIdx.x;
    if (b >= BATCH) return;
    float loc[ZDIM];
    #pragma unroll
    for (int z = 0; z < ZDIM; ++z) loc[z] = state[b * SDIM + ADIM + z];
    float lp[EDIM];
    #pragma unroll
    for (int e = 0; e < EDIM; ++e) {
        float s = loc_proj_b[e];
        #pragma unroll
        for (int z = 0; z < ZDIM; ++z) s += loc_proj_w[e * ZDIM + z] * loc[z];
        lp[e] = s;
    }
    float v[EDIM];
    #pragma unroll
    for (int e = 0; e < EDIM; ++e) {
        float s = lp_in_b[2 * EDIM + e];
        #pragma unroll
        for (int j = 0; j < EDIM; ++j) s += lp_in_w[(2 * EDIM + e) * EDIM + j] * lp[j];
        v[e] = s;
    }
    float d[EDIM];
    #pragma unroll
    for (int e = 0; e < EDIM; ++e) {
        float s = lp_out_b[e];
        #pragma unroll
        for (int j = 0; j < EDIM; ++j) s += lp_out_w[e * EDIM + j] * v[j];
        d[e] = s - lp[e];
    }
    #pragma unroll
    for (int z = 0; z < ZDIM; ++z) {
        float s = loc_back_b[z];
        #pragma unroll
        for (int e = 0; e < EDIM; ++e) s += loc_back_w[z * EDIM + e] * d[e];
        dloc[b * ZDIM + z] = s;
    }
}

__global__ void combine_kernel(float* __restrict__ out,
                               const float* __restrict__ state,
                               const float* __restrict__ dh,
                               const float* __restrict__ dloc)
{
    int i = blockIdx.x * blockDim.x + threadIdx.x;
    if (i >= BATCH * SDIM) return;
    int b = i / SDIM, j = i % SDIM;
    float o = out[i];
    if (j < ADIM)              o += 0.1f * (dh[b * ADIM + j] - state[i]);
    else if (j < ADIM + ZDIM)  o += 0.1f * dloc[b * ZDIM + (j - ADIM)];
    out[i] = o;
}

// ---------------------------------------------------------------------------
// Launch
// ---------------------------------------------------------------------------
extern "C" void kernel_launch(void* const* d_in, const int* in_sizes, int n_in,
                              void* d_out, int out_size)
{
    const float* t          = (const float*)d_in[0];
    const float* state      = (const float*)d_in[1];
    const float* W0         = (const float*)d_in[2];
    const float* b0         = (const float*)d_in[3];
    const float* rW1        = (const float*)d_in[4];
    const float* rb1        = (const float*)d_in[5];
    const float* rW2        = (const float*)d_in[6];
    const float* rb2        = (const float*)d_in[7];
    const float* Wf         = (const float*)d_in[8];
    const float* bf_        = (const float*)d_in[9];
    const float* lp_in_w    = (const float*)d_in[10];
    const float* lp_in_b    = (const float*)d_in[11];
    const float* lp_out_w   = (const float*)d_in[12];
    const float* lp_out_b   = (const float*)d_in[13];
    const float* ta_in_w    = (const float*)d_in[14];
    const float* ta_in_b    = (const float*)d_in[15];
    const float* ta_out_w   = (const float*)d_in[16];
    const float* ta_out_b   = (const float*)d_in[17];
    const float* loc_proj_w = (const float*)d_in[18];
    const float* loc_proj_b = (const float*)d_in[19];
    const float* loc_back_w = (const float*)d_in[20];
    const float* loc_back_b = (const float*)d_in[21];
    float* out = (float*)d_out;

    __half *x, *hA, *hB, *u, *v;
    float *dh, *dloc;
    __half *W0h, *W1h, *W2h, *Wfh, *TIh, *TOh;
    cudaGetSymbolAddress((void**)&x,  g_x);
    cudaGetSymbolAddress((void**)&hA, g_hA);
    cudaGetSymbolAddress((void**)&hB, g_hB);
    cudaGetSymbolAddress((void**)&u,  g_u);
    cudaGetSymbolAddress((void**)&v,  g_v);
    cudaGetSymbolAddress((void**)&dh, g_dh);
    cudaGetSymbolAddress((void**)&dloc, g_dloc);
    cudaGetSymbolAddress((void**)&W0h, g_W0);
    cudaGetSymbolAddress((void**)&W1h, g_W1);
    cudaGetSymbolAddress((void**)&W2h, g_W2);
    cudaGetSymbolAddress((void**)&Wfh, g_Wf);
    cudaGetSymbolAddress((void**)&TIh, g_TI);
    cudaGetSymbolAddress((void**)&TOh, g_TO);

    cudaFuncSetAttribute(gemm_f16, cudaFuncAttributeMaxDynamicSharedMemorySize, SMEM_DYN);

    // --- prologue (2 launches) ---
    conv_all_kernel<<<CDIV(N_ALL / 4, 256), 256>>>(rW1, rW2, Wf, ta_in_w, ta_out_w);
    prep_kernel<<<CDIV(N_CW0 + BATCH * KX, 256), 256>>>(W0, state, t);

    // --- main chain ---
    dim3 blk(512);
    dim3 gH(HDIM / 128, BATCH / 256);           // (8, 32)

    // h = relu(x @ W0^T + b0)
    gemm_f16<<<gH, blk, SMEM_DYN>>>(x, KX, W0h, KX, b0, nullptr, 0,
                                    nullptr, hA, HDIM, HDIM, KX, EPI_RELU);

    __half *hc = hA, *hn = hB;
    for (int i = 0; i < RB; ++i) {
        const size_t wo = (size_t)i * HDIM * HDIM;
        // u = tanh(h @ W1^T + b1)
        gemm_f16<<<gH, blk, SMEM_DYN>>>(hc, HDIM, W1h + wo, HDIM, rb1 + i * HDIM,
                                        nullptr, 0,
                                        nullptr, u, HDIM, HDIM, HDIM, EPI_TANH);
        // h' = tanh(u @ W2^T + b2 + h)
        gemm_f16<<<gH, blk, SMEM_DYN>>>(u, HDIM, W2h + wo, HDIM, rb2 + i * HDIM,
                                        hc, HDIM,
                                        nullptr, hn, HDIM, HDIM, HDIM, EPI_TANH);
        __half* tmp = hc; hc = hn; hn = tmp;
    }

    // core = h @ Wf^T + bf -> f32 out
    dim3 gF(CDIV(SDIM, 128), BATCH / 256);      // (3, 32)
    gemm_f16<<<gF, blk, SMEM_DYN>>>(hc, HDIM, Wfh, HDIM, bf_, nullptr, 0,
                                    out, nullptr, SDIM, SDIM, HDIM, EPI_NONE);

    // --- independent side path (h_part = first 256 cols of x) ---
    dim3 gT(ADIM / 128, BATCH / 256);           // (2, 32)
    gemm_f16<<<gT, blk, SMEM_DYN>>>(x, KX, TIh, ADIM, ta_in_b + 2 * ADIM, nullptr, 0,
                                    nullptr, v, ADIM, ADIM, ADIM, EPI_NONE);
    gemm_f16<<<gT, blk, SMEM_DYN>>>(v, ADIM, TOh, ADIM, ta_out_b, nullptr, 0,
                                    dh, nullptr, ADIM, ADIM, ADIM, EPI_NONE);
    loc_kernel<<<CDIV(BATCH, 256), 256>>>(state, loc_proj_w, loc_proj_b,
                                          lp_in_w, lp_in_b, lp_out_w, lp_out_b,
                                          loc_back_w, loc_back_b, dloc);

    combine_kernel<<<CDIV(BATCH * SDIM, 256), 256>>>(out, state, dh, dloc);
}